// round 5
// baseline (speedup 1.0000x reference)
#include <cuda_runtime.h>

#define NDEPTH 4
typedef unsigned long long u64;

__device__ __forceinline__ u64 ffma2(u64 a, u64 b, u64 c){
    u64 d; asm("fma.rn.f32x2 %0, %1, %2, %3;" : "=l"(d) : "l"(a), "l"(b), "l"(c)); return d;
}
__device__ __forceinline__ u64 fpack2(float x, float y){
    u64 d; asm("mov.b64 %0, {%1, %2};" : "=l"(d) : "f"(x), "f"(y)); return d;
}
__device__ __forceinline__ float2 funpack2(u64 a){
    float x, y; asm("mov.b64 {%0, %1}, %2;" : "=f"(x), "=f"(y) : "l"(a)); return make_float2(x, y);
}

// ---------------- scratch (device globals) ----------------
__device__ float  g_h0[8*64*65536];
__device__ float  g_h1[8*64*65536];
__device__ float2 g_f1[8*64*256*16];
__device__ float2 g_modes[8*64*256];
__device__ float2 g_mixed[8*64*256];               // mixedT [b][ky][kx][o]
__device__ float2 g_G[8*256*16*64];                // [b][y][ky][c]
__device__ float2 g_wt[NDEPTH*256*64*64];          // [d][m][i][o]
__device__ float  g_ec[16*256], g_es[16*256];      // fwd: (cos, -sin) split
__device__ float  g_ic[16*256], g_is[16*256];      // inv-W scaled tables

// ---------------- prep: DFT tables ----------------
__global__ void kprep(){
    int idx = blockIdx.x * 256 + threadIdx.x;      // 4096 = [ky][x]
    int x = idx & 255, ky = idx >> 8;
    float ang = 6.283185307179586f * (float)((ky * x) & 255) / 256.f;
    float c = cosf(ang), s = sinf(ang);
    g_ec[idx] = c; g_es[idx] = -s;
    const float sc = 1.f / 65536.f;
    g_ic[idx] = (ky == 0) ? sc : 2.f * sc * c;
    g_is[idx] = (ky == 0) ? 0.f : -2.f * sc * s;
}

// ---------------- spectral weight transpose: [d][i][o][kx][ky] -> [d][m][i][o] ----------------
__global__ void ktw(const float* __restrict__ wre, const float* __restrict__ wim){
    int idx = blockIdx.x * 256 + threadIdx.x;
    int ky = idx & 15, kx = (idx >> 4) & 15, o = (idx >> 8) & 63, i = (idx >> 14) & 63, d = idx >> 20;
    int m = kx * 16 + ky;
    g_wt[((d * 256 + m) * 64 + i) * 64 + o] = make_float2(wre[idx], wim[idx]);
}

// ---------------- fc0: 3 -> 64 channels, float4 ----------------
__global__ void kfc0(const float* __restrict__ x, const float* __restrict__ w,
                     const float* __restrict__ bv, float* __restrict__ out){
    int idx = blockIdx.x * 256 + threadIdx.x;      // 8*64*16384
    int p4 = idx & 16383;
    int c  = (idx >> 14) & 63;
    int b  = idx >> 20;
    const float* xb = x + (size_t)b * 3 * 65536 + p4 * 4;
    float4 a0 = *(const float4*)&xb[0];
    float4 a1 = *(const float4*)&xb[65536];
    float4 a2 = *(const float4*)&xb[131072];
    float w0 = w[c*3], w1 = w[c*3+1], w2 = w[c*3+2], bb = bv[c];
    float4 r;
    r.x = bb + a0.x*w0 + a1.x*w1 + a2.x*w2;
    r.y = bb + a0.y*w0 + a1.y*w1 + a2.y*w2;
    r.z = bb + a0.z*w0 + a1.z*w1 + a2.z*w2;
    r.w = bb + a0.w*w0 + a1.w*w1 + a2.w*w2;
    *(float4*)&out[(size_t)idx * 4] = r;
}

// ---------------- fwd DFT along W (256 -> 16 modes), f32x2 register-blocked ----------------
// block: 128 rows, 256 threads, thread tile 2 rows x 4 ky (re,im packed)
__global__ void kfwd1(const float* __restrict__ hin, float2* __restrict__ f1){
    extern __shared__ __align__(16) u64 dsm1[];
    u64* sh2 = dsm1;                               // [128][34]  (h,h) dup per x chunk
    u64* tcs = dsm1 + 128 * 34;                    // [256][18]  (cos,-sin)
    int tid = threadIdx.x;                         // 256
    size_t rowbase = (size_t)blockIdx.x * 128;
    for (int idx = tid; idx < 4096; idx += 256){
        int ky = idx & 15, x = idx >> 4;
        tcs[x * 18 + ky] = fpack2(g_ec[ky * 256 + x], g_es[ky * 256 + x]);
    }
    int r0 = (tid >> 2) * 2;
    int k0 = (tid & 3) * 4;
    u64 acc[2][4];
    #pragma unroll
    for (int a = 0; a < 2; ++a)
        #pragma unroll
        for (int k = 0; k < 4; ++k) acc[a][k] = 0ull;

    for (int ch = 0; ch < 8; ++ch){
        int xb = ch * 32;
        __syncthreads();
        for (int idx = tid; idx < 1024; idx += 256){
            int r = idx >> 3, xq = (idx & 7) * 4;
            float4 v = *(const float4*)&hin[(rowbase + r) * 256 + xb + xq];
            u64* dst = &sh2[r * 34 + xq];
            dst[0] = fpack2(v.x, v.x);
            dst[1] = fpack2(v.y, v.y);
            dst[2] = fpack2(v.z, v.z);
            dst[3] = fpack2(v.w, v.w);
        }
        __syncthreads();
        #pragma unroll 4
        for (int xl = 0; xl < 32; ++xl){
            int x = xb + xl;
            u64 h0 = sh2[r0 * 34 + xl];
            u64 h1 = sh2[(r0 + 1) * 34 + xl];
            ulonglong2 t0 = *(const ulonglong2*)&tcs[x * 18 + k0];
            ulonglong2 t1 = *(const ulonglong2*)&tcs[x * 18 + k0 + 2];
            acc[0][0] = ffma2(h0, t0.x, acc[0][0]);
            acc[0][1] = ffma2(h0, t0.y, acc[0][1]);
            acc[0][2] = ffma2(h0, t1.x, acc[0][2]);
            acc[0][3] = ffma2(h0, t1.y, acc[0][3]);
            acc[1][0] = ffma2(h1, t0.x, acc[1][0]);
            acc[1][1] = ffma2(h1, t0.y, acc[1][1]);
            acc[1][2] = ffma2(h1, t1.x, acc[1][2]);
            acc[1][3] = ffma2(h1, t1.y, acc[1][3]);
        }
    }
    #pragma unroll
    for (int a = 0; a < 2; ++a)
        #pragma unroll
        for (int k = 0; k < 4; ++k)
            f1[(rowbase + r0 + a) * 16 + k0 + k] = funpack2(acc[a][k]);
}

// ---------------- fwd DFT along H (256 -> 16 modes), split-K ----------------
__global__ void kfwd2(const float2* __restrict__ f1, float2* __restrict__ modes){
    __shared__ float2 sf[4096];
    __shared__ float ct[256], st[256];
    __shared__ float2 sred[256];
    int tid = threadIdx.x;                         // 512
    if (tid < 256){
        float ang = 6.283185307179586f * (float)tid / 256.f;
        ct[tid] = cosf(ang); st[tid] = sinf(ang);
    }
    int bc = blockIdx.x;
    const float2* src = f1 + (size_t)bc * 4096;
    for (int idx = tid; idx < 4096; idx += 512) sf[idx] = src[idx];
    __syncthreads();
    int outi = tid & 255;
    int kx = outi >> 4, ky = outi & 15;
    int yb = (tid >> 8) * 128;
    float re = 0.f, im = 0.f;
    #pragma unroll 8
    for (int yy = yb; yy < yb + 128; ++yy){
        float2 v = sf[yy * 16 + ky];
        int t = (kx * yy) & 255;
        float c = ct[t], s = st[t];
        re += v.x * c + v.y * s;
        im += v.y * c - v.x * s;
    }
    if (tid >= 256) sred[outi] = make_float2(re, im);
    __syncthreads();
    if (tid < 256){
        float2 o = sred[outi];
        modes[bc * 256 + outi] = make_float2(re + o.x, im + o.y);
    }
}

// ---------------- mode mixing -> mixedT [b][ky][kx][o] ----------------
__global__ void kmix(const float2* __restrict__ modes, const float2* __restrict__ wt,
                     float2* __restrict__ mixedT){
    __shared__ float2 swt[4096];
    __shared__ float2 sin_[512];
    int tid = threadIdx.x, m = blockIdx.x;
    int ky = m & 15, kx = m >> 4;
    const float2* wsrc = wt + (size_t)m * 4096;
    for (int idx = tid; idx < 4096; idx += 256) swt[idx] = wsrc[idx];
    for (int idx = tid; idx < 512; idx += 256){
        int b = idx >> 6, i = idx & 63;
        sin_[idx] = modes[(b * 64 + i) * 256 + m];
    }
    __syncthreads();
    int o = tid & 63;
    for (int half = 0; half < 2; ++half){
        int b = (tid >> 6) + half * 4;
        float re = 0.f, im = 0.f;
        #pragma unroll 8
        for (int i = 0; i < 64; ++i){
            float2 a = sin_[b * 64 + i];
            float2 wv = swt[i * 64 + o];
            re += a.x * wv.x - a.y * wv.y;
            im += a.x * wv.y + a.y * wv.x;
        }
        mixedT[((b * 16 + ky) * 16 + kx) * 64 + o] = make_float2(re, im);
    }
}

// ---------------- inv DFT along H (16 -> 256): G [b][y][ky][c] ----------------
__global__ void kinv1(const float2* __restrict__ mixedT, float2* __restrict__ G){
    __shared__ float2 sm[1024];                    // [kx][c]
    __shared__ float ct[256], st[256];
    int tid = threadIdx.x;                         // 256
    int ky = blockIdx.x & 15, yg = (blockIdx.x >> 4) & 15, b = blockIdx.x >> 8;
    {
        float ang = 6.283185307179586f * (float)tid / 256.f;
        ct[tid] = cosf(ang); st[tid] = sinf(ang);
    }
    const float2* src = mixedT + (size_t)(b * 16 + ky) * 1024;
    for (int idx = tid; idx < 1024; idx += 256) sm[idx] = src[idx];
    __syncthreads();
    int c = tid & 63, yl = tid >> 6;
    #pragma unroll
    for (int yi = 0; yi < 4; ++yi){
        int yy = yg * 16 + yl * 4 + yi;
        float re = 0.f, im = 0.f;
        #pragma unroll
        for (int kx = 0; kx < 16; ++kx){
            float2 v = sm[kx * 64 + c];
            int t = (kx * yy) & 255;
            float cc = ct[t], ss = st[t];
            re += v.x * cc - v.y * ss;
            im += v.x * ss + v.y * cc;
        }
        G[((size_t)(b * 256 + yy) * 16 + ky) * 64 + c] = make_float2(re, im);
    }
}

// ---------------- fused: 1x1 conv + inv DFT along W + bias + relu (f32x2) ----------------
// dyn smem: 77056 B
#define CONV1(oo, wv) \
    acc[oo][0] = ffma2(wv, h2.x, acc[oo][0]); \
    acc[oo][1] = ffma2(wv, h2.y, acc[oo][1]);
#define INV1(oo, gx, gy) \
    acc[oo][0] = ffma2(gx, A2v.x, acc[oo][0]); \
    acc[oo][0] = ffma2(gy, B2v.x, acc[oo][0]); \
    acc[oo][1] = ffma2(gx, A2v.y, acc[oo][1]); \
    acc[oo][1] = ffma2(gy, B2v.y, acc[oo][1]);

__global__ __launch_bounds__(256) void kfused(
        const float* __restrict__ hin, const float2* __restrict__ G,
        const float* __restrict__ ww, const float* __restrict__ wb,
        float* __restrict__ hout){
    extern __shared__ __align__(16) u64 dsm2[];
    u64*   swc2 = dsm2;                            // [64][66]  (w,w) [i][o]
    u64*   sgx2 = swc2 + 64 * 66;                  // [16][66]
    u64*   sgy2 = sgx2 + 16 * 66;                  // [16][66]
    float* sh   = (float*)(sgy2 + 16 * 66);        // [64][68]
    float* sA   = sh + 64 * 68;                    // [16][68]
    float* sB   = sA + 16 * 68;                    // [16][68]
    float* sb   = sB + 16 * 68;                    // [64]
    int tid = threadIdx.x;                         // 256
    int xc = (blockIdx.x & 3) << 6;
    int y  = (blockIdx.x >> 2) & 255;
    int b  = blockIdx.x >> 10;

    const float* hb = hin + ((size_t)(b * 64) * 256 + y) * 256 + xc;
    for (int idx = tid; idx < 4096; idx += 256){
        int a = idx >> 6, c = idx & 63;
        sh[a * 68 + c] = hb[(size_t)a * 65536 + c];
        float wv = ww[idx];                        // w[o=a][i=c]
        swc2[c * 66 + a] = fpack2(wv, wv);
    }
    const float2* Gb = G + ((size_t)(b * 256) + y) * 1024;
    for (int idx = tid; idx < 1024; idx += 256){
        int ky = idx >> 6, o = idx & 63;
        float2 g = Gb[ky * 64 + o];
        sgx2[ky * 66 + o] = fpack2(g.x, g.x);
        sgy2[ky * 66 + o] = fpack2(g.y, g.y);
        sA[ky * 68 + o] = g_ic[ky * 256 + xc + o];
        sB[ky * 68 + o] = g_is[ky * 256 + xc + o];
    }
    if (tid < 64) sb[tid] = wb[tid];
    __syncthreads();

    int o0 = (tid >> 4) * 4;
    int x0 = (tid & 15) * 4;
    u64 acc[4][2];
    #pragma unroll
    for (int oo = 0; oo < 4; ++oo){
        float bv = sb[o0 + oo];
        acc[oo][0] = acc[oo][1] = fpack2(bv, bv);
    }
    #pragma unroll 4
    for (int i = 0; i < 64; ++i){
        ulonglong2 h2  = *(const ulonglong2*)&sh[i * 68 + x0];
        ulonglong2 w01 = *(const ulonglong2*)&swc2[i * 66 + o0];
        ulonglong2 w23 = *(const ulonglong2*)&swc2[i * 66 + o0 + 2];
        CONV1(0, w01.x) CONV1(1, w01.y) CONV1(2, w23.x) CONV1(3, w23.y)
    }
    #pragma unroll 4
    for (int ky = 0; ky < 16; ++ky){
        ulonglong2 A2v  = *(const ulonglong2*)&sA[ky * 68 + x0];
        ulonglong2 B2v  = *(const ulonglong2*)&sB[ky * 68 + x0];
        ulonglong2 gx01 = *(const ulonglong2*)&sgx2[ky * 66 + o0];
        ulonglong2 gx23 = *(const ulonglong2*)&sgx2[ky * 66 + o0 + 2];
        ulonglong2 gy01 = *(const ulonglong2*)&sgy2[ky * 66 + o0];
        ulonglong2 gy23 = *(const ulonglong2*)&sgy2[ky * 66 + o0 + 2];
        INV1(0, gx01.x, gy01.x) INV1(1, gx01.y, gy01.y)
        INV1(2, gx23.x, gy23.x) INV1(3, gx23.y, gy23.y)
    }
    float* ob = hout + ((size_t)(b * 64 + o0) * 256 + y) * 256 + xc + x0;
    #pragma unroll
    for (int oo = 0; oo < 4; ++oo){
        float2 p0 = funpack2(acc[oo][0]);
        float2 p1 = funpack2(acc[oo][1]);
        float4 v = make_float4(fmaxf(p0.x, 0.f), fmaxf(p0.y, 0.f),
                               fmaxf(p1.x, 0.f), fmaxf(p1.y, 0.f));
        *(float4*)&ob[(size_t)oo * 65536] = v;
    }
}

// ---------------- fused MLP head (f32x2) ----------------
// dyn smem: 105472 B
#define HSTEP(mp, wv) \
    acch[mp][0] = ffma2(wv, h01.x, acch[mp][0]); \
    acch[mp][1] = ffma2(wv, h01.y, acch[mp][1]); \
    acch[mp][2] = ffma2(wv, h23.x, acch[mp][2]); \
    acch[mp][3] = ffma2(wv, h23.y, acch[mp][3]);

__global__ __launch_bounds__(256) void khead(
        const float* __restrict__ hin,
        const float* __restrict__ w1, const float* __restrict__ b1,
        const float* __restrict__ w2, const float* __restrict__ b2,
        float* __restrict__ out){
    extern __shared__ __align__(16) u64 dsm3[];
    u64*   sh2  = dsm3;                            // [64][68]  (h,h) dup
    float* sw1t = (float*)(sh2 + 64 * 68);         // [64][132] w1^T [c][m]
    float* shid = sw1t + 64 * 132;                 // [128][68]
    float* sw2s = shid + 128 * 68;                 // [384]
    float* sb1s = sw2s + 384;                      // [128]
    int tid = threadIdx.x;                         // 256
    int xc = (blockIdx.x & 3) << 6;
    int y  = (blockIdx.x >> 2) & 255;
    int b  = blockIdx.x >> 10;

    const float* hb = hin + ((size_t)(b * 64) * 256 + y) * 256 + xc;
    for (int idx = tid; idx < 4096; idx += 256){
        int c = idx >> 6, xl = idx & 63;
        float v = hb[(size_t)c * 65536 + xl];
        sh2[c * 68 + xl] = fpack2(v, v);
    }
    for (int idx = tid; idx < 8192; idx += 256){
        int m = idx >> 6, c = idx & 63;
        sw1t[c * 132 + m] = w1[idx];               // w1 [m][c]
    }
    for (int idx = tid; idx < 384; idx += 256) sw2s[idx] = w2[idx];
    if (tid < 128) sb1s[tid] = b1[tid];
    __syncthreads();

    int m0 = (tid >> 4) * 8;
    int x0 = (tid & 15) * 4;
    u64 acch[4][4];
    #pragma unroll
    for (int mp = 0; mp < 4; ++mp){
        float2 bp = *(const float2*)&sb1s[m0 + 2 * mp];
        u64 bb = fpack2(bp.x, bp.y);
        #pragma unroll
        for (int xx = 0; xx < 4; ++xx) acch[mp][xx] = bb;
    }
    #pragma unroll 4
    for (int c = 0; c < 64; ++c){
        ulonglong2 h01 = *(const ulonglong2*)&sh2[c * 68 + x0];
        ulonglong2 h23 = *(const ulonglong2*)&sh2[c * 68 + x0 + 2];
        ulonglong2 wA  = *(const ulonglong2*)&sw1t[c * 132 + m0];
        ulonglong2 wB  = *(const ulonglong2*)&sw1t[c * 132 + m0 + 4];
        HSTEP(0, wA.x) HSTEP(1, wA.y) HSTEP(2, wB.x) HSTEP(3, wB.y)
    }
    #pragma unroll
    for (int mp = 0; mp < 4; ++mp)
        #pragma unroll
        for (int xx = 0; xx < 4; ++xx){
            float2 v = funpack2(acch[mp][xx]);
            shid[(m0 + 2 * mp)     * 68 + x0 + xx] = fmaxf(v.x, 0.f);
            shid[(m0 + 2 * mp + 1) * 68 + x0 + xx] = fmaxf(v.y, 0.f);
        }
    __syncthreads();
    if (tid < 192){
        int o = tid >> 6, xl = tid & 63;
        float a = b2[o];
        #pragma unroll 8
        for (int m = 0; m < 128; ++m)
            a = fmaf(shid[m * 68 + xl], sw2s[o * 128 + m], a);
        out[((size_t)(b * 3 + o) * 256 + y) * 256 + xc + xl] = a;
    }
}

// ---------------- host ----------------
extern "C" void kernel_launch(void* const* d_in, const int* in_sizes, int n_in,
                              void* d_out, int out_size) {
    const float* x       = (const float*)d_in[0];
    const float* fc0_w   = (const float*)d_in[1];
    const float* fc0_b   = (const float*)d_in[2];
    const float* spec_re = (const float*)d_in[3];
    const float* spec_im = (const float*)d_in[4];
    const float* w_w     = (const float*)d_in[5];
    const float* w_b     = (const float*)d_in[6];
    const float* fc1_w   = (const float*)d_in[7];
    const float* fc1_b   = (const float*)d_in[8];
    const float* fc2_w   = (const float*)d_in[9];
    const float* fc2_b   = (const float*)d_in[10];

    float  *h0, *h1;
    float2 *f1, *mo, *mx, *G, *wt;
    cudaGetSymbolAddress((void**)&h0, g_h0);
    cudaGetSymbolAddress((void**)&h1, g_h1);
    cudaGetSymbolAddress((void**)&f1, g_f1);
    cudaGetSymbolAddress((void**)&mo, g_modes);
    cudaGetSymbolAddress((void**)&mx, g_mixed);
    cudaGetSymbolAddress((void**)&G,  g_G);
    cudaGetSymbolAddress((void**)&wt, g_wt);

    cudaFuncSetAttribute(kfwd1,  cudaFuncAttributeMaxDynamicSharedMemorySize, 71680);
    cudaFuncSetAttribute(kfused, cudaFuncAttributeMaxDynamicSharedMemorySize, 77056);
    cudaFuncSetAttribute(khead,  cudaFuncAttributeMaxDynamicSharedMemorySize, 105472);

    kprep<<<16, 256>>>();
    ktw<<<16384, 256>>>(spec_re, spec_im);
    kfc0<<<32768, 256>>>(x, fc0_w, fc0_b, h0);

    float* hin = h0;
    float* hout = h1;
    for (int d = 0; d < NDEPTH; ++d) {
        kfwd1<<<1024, 256, 71680>>>(hin, f1);
        kfwd2<<<512, 512>>>(f1, mo);
        kmix<<<256, 256>>>(mo, wt + (size_t)d * 256 * 4096, mx);
        kinv1<<<2048, 256>>>(mx, G);
        kfused<<<8192, 256, 77056>>>(hin, G, w_w + d * 4096, w_b + d * 64, hout);
        float* t = hin; hin = hout; hout = t;
    }
    khead<<<8192, 256, 105472>>>(hin, fc1_w, fc1_b, fc2_w, fc2_b, (float*)d_out);
}

// round 6
// speedup vs baseline: 1.0011x; 1.0011x over previous
#include <cuda_runtime.h>

#define NDEPTH 4
typedef unsigned long long u64;

__device__ __forceinline__ u64 ffma2(u64 a, u64 b, u64 c){
    u64 d; asm("fma.rn.f32x2 %0, %1, %2, %3;" : "=l"(d) : "l"(a), "l"(b), "l"(c)); return d;
}
__device__ __forceinline__ u64 fpack2(float x, float y){
    u64 d; asm("mov.b64 %0, {%1, %2};" : "=l"(d) : "f"(x), "f"(y)); return d;
}
__device__ __forceinline__ float2 funpack2(u64 a){
    float x, y; asm("mov.b64 {%0, %1}, %2;" : "=f"(x), "=f"(y) : "l"(a)); return make_float2(x, y);
}

// ---------------- scratch (device globals) ----------------
__device__ float  g_h0[8*64*65536];
__device__ float  g_h1[8*64*65536];
__device__ float2 g_f1[8*64*256*16];
__device__ float2 g_modes[8*64*256];
__device__ float2 g_mixed[8*64*256];               // mixedT [b][ky][kx][o]
__device__ float2 g_G[8*256*16*64];                // [b][y][ky][c]
__device__ float2 g_wt[NDEPTH*256*64*64];          // [d][m][i][o]
__device__ float  g_ec[16*256], g_es[16*256];      // fwd: (cos, -sin) split
__device__ float  g_ic[16*256], g_is[16*256];      // inv-W scaled tables

// ---------------- prep: DFT tables ----------------
__global__ void kprep(){
    int idx = blockIdx.x * 256 + threadIdx.x;      // 4096 = [ky][x]
    int x = idx & 255, ky = idx >> 8;
    float ang = 6.283185307179586f * (float)((ky * x) & 255) / 256.f;
    float c = cosf(ang), s = sinf(ang);
    g_ec[idx] = c; g_es[idx] = -s;
    const float sc = 1.f / 65536.f;
    g_ic[idx] = (ky == 0) ? sc : 2.f * sc * c;
    g_is[idx] = (ky == 0) ? 0.f : -2.f * sc * s;
}

// ---------------- spectral weight transpose: [d][i][o][kx][ky] -> [d][m][i][o] ----------------
__global__ void ktw(const float* __restrict__ wre, const float* __restrict__ wim){
    int idx = blockIdx.x * 256 + threadIdx.x;
    int ky = idx & 15, kx = (idx >> 4) & 15, o = (idx >> 8) & 63, i = (idx >> 14) & 63, d = idx >> 20;
    int m = kx * 16 + ky;
    g_wt[((d * 256 + m) * 64 + i) * 64 + o] = make_float2(wre[idx], wim[idx]);
}

// ---------------- fc0: 3 -> 64 channels, float4 ----------------
__global__ void kfc0(const float* __restrict__ x, const float* __restrict__ w,
                     const float* __restrict__ bv, float* __restrict__ out){
    int idx = blockIdx.x * 256 + threadIdx.x;      // 8*64*16384
    int p4 = idx & 16383;
    int c  = (idx >> 14) & 63;
    int b  = idx >> 20;
    const float* xb = x + (size_t)b * 3 * 65536 + p4 * 4;
    float4 a0 = *(const float4*)&xb[0];
    float4 a1 = *(const float4*)&xb[65536];
    float4 a2 = *(const float4*)&xb[131072];
    float w0 = w[c*3], w1 = w[c*3+1], w2 = w[c*3+2], bb = bv[c];
    float4 r;
    r.x = bb + a0.x*w0 + a1.x*w1 + a2.x*w2;
    r.y = bb + a0.y*w0 + a1.y*w1 + a2.y*w2;
    r.z = bb + a0.z*w0 + a1.z*w1 + a2.z*w2;
    r.w = bb + a0.w*w0 + a1.w*w1 + a2.w*w2;
    *(float4*)&out[(size_t)idx * 4] = r;
}

// ---------------- fwd DFT along W (256 -> 16 modes), f32x2 register-blocked ----------------
// block: 128 rows, 256 threads, thread tile 2 rows x 4 ky (re,im packed)
__global__ void kfwd1(const float* __restrict__ hin, float2* __restrict__ f1){
    extern __shared__ __align__(16) u64 dsm1[];
    u64* sh2 = dsm1;                               // [128][34]  (h,h) dup per x chunk
    u64* tcs = dsm1 + 128 * 34;                    // [256][18]  (cos,-sin)
    int tid = threadIdx.x;                         // 256
    size_t rowbase = (size_t)blockIdx.x * 128;
    for (int idx = tid; idx < 4096; idx += 256){
        int ky = idx & 15, x = idx >> 4;
        tcs[x * 18 + ky] = fpack2(g_ec[ky * 256 + x], g_es[ky * 256 + x]);
    }
    int r0 = (tid >> 2) * 2;
    int k0 = (tid & 3) * 4;
    u64 acc[2][4];
    #pragma unroll
    for (int a = 0; a < 2; ++a)
        #pragma unroll
        for (int k = 0; k < 4; ++k) acc[a][k] = 0ull;

    for (int ch = 0; ch < 8; ++ch){
        int xb = ch * 32;
        __syncthreads();
        for (int idx = tid; idx < 1024; idx += 256){
            int r = idx >> 3, xq = (idx & 7) * 4;
            float4 v = *(const float4*)&hin[(rowbase + r) * 256 + xb + xq];
            u64* dst = &sh2[r * 34 + xq];
            dst[0] = fpack2(v.x, v.x);
            dst[1] = fpack2(v.y, v.y);
            dst[2] = fpack2(v.z, v.z);
            dst[3] = fpack2(v.w, v.w);
        }
        __syncthreads();
        #pragma unroll 4
        for (int xl = 0; xl < 32; ++xl){
            int x = xb + xl;
            u64 h0 = sh2[r0 * 34 + xl];
            u64 h1 = sh2[(r0 + 1) * 34 + xl];
            ulonglong2 t0 = *(const ulonglong2*)&tcs[x * 18 + k0];
            ulonglong2 t1 = *(const ulonglong2*)&tcs[x * 18 + k0 + 2];
            acc[0][0] = ffma2(h0, t0.x, acc[0][0]);
            acc[0][1] = ffma2(h0, t0.y, acc[0][1]);
            acc[0][2] = ffma2(h0, t1.x, acc[0][2]);
            acc[0][3] = ffma2(h0, t1.y, acc[0][3]);
            acc[1][0] = ffma2(h1, t0.x, acc[1][0]);
            acc[1][1] = ffma2(h1, t0.y, acc[1][1]);
            acc[1][2] = ffma2(h1, t1.x, acc[1][2]);
            acc[1][3] = ffma2(h1, t1.y, acc[1][3]);
        }
    }
    #pragma unroll
    for (int a = 0; a < 2; ++a)
        #pragma unroll
        for (int k = 0; k < 4; ++k)
            f1[(rowbase + r0 + a) * 16 + k0 + k] = funpack2(acc[a][k]);
}

// ---------------- fwd DFT along H (256 -> 16 modes), split-K ----------------
__global__ void kfwd2(const float2* __restrict__ f1, float2* __restrict__ modes){
    __shared__ float2 sf[4096];
    __shared__ float ct[256], st[256];
    __shared__ float2 sred[256];
    int tid = threadIdx.x;                         // 512
    if (tid < 256){
        float ang = 6.283185307179586f * (float)tid / 256.f;
        ct[tid] = cosf(ang); st[tid] = sinf(ang);
    }
    int bc = blockIdx.x;
    const float2* src = f1 + (size_t)bc * 4096;
    for (int idx = tid; idx < 4096; idx += 512) sf[idx] = src[idx];
    __syncthreads();
    int outi = tid & 255;
    int kx = outi >> 4, ky = outi & 15;
    int yb = (tid >> 8) * 128;
    float re = 0.f, im = 0.f;
    #pragma unroll 8
    for (int yy = yb; yy < yb + 128; ++yy){
        float2 v = sf[yy * 16 + ky];
        int t = (kx * yy) & 255;
        float c = ct[t], s = st[t];
        re += v.x * c + v.y * s;
        im += v.y * c - v.x * s;
    }
    if (tid >= 256) sred[outi] = make_float2(re, im);
    __syncthreads();
    if (tid < 256){
        float2 o = sred[outi];
        modes[bc * 256 + outi] = make_float2(re + o.x, im + o.y);
    }
}

// ---------------- mode mixing -> mixedT [b][ky][kx][o] ----------------
__global__ void kmix(const float2* __restrict__ modes, const float2* __restrict__ wt,
                     float2* __restrict__ mixedT){
    __shared__ float2 swt[4096];
    __shared__ float2 sin_[512];
    int tid = threadIdx.x, m = blockIdx.x;
    int ky = m & 15, kx = m >> 4;
    const float2* wsrc = wt + (size_t)m * 4096;
    for (int idx = tid; idx < 4096; idx += 256) swt[idx] = wsrc[idx];
    for (int idx = tid; idx < 512; idx += 256){
        int b = idx >> 6, i = idx & 63;
        sin_[idx] = modes[(b * 64 + i) * 256 + m];
    }
    __syncthreads();
    int o = tid & 63;
    for (int half = 0; half < 2; ++half){
        int b = (tid >> 6) + half * 4;
        float re = 0.f, im = 0.f;
        #pragma unroll 8
        for (int i = 0; i < 64; ++i){
            float2 a = sin_[b * 64 + i];
            float2 wv = swt[i * 64 + o];
            re += a.x * wv.x - a.y * wv.y;
            im += a.x * wv.y + a.y * wv.x;
        }
        mixedT[((b * 16 + ky) * 16 + kx) * 64 + o] = make_float2(re, im);
    }
}

// ---------------- inv DFT along H (16 -> 256): G [b][y][ky][c] ----------------
__global__ void kinv1(const float2* __restrict__ mixedT, float2* __restrict__ G){
    __shared__ float2 sm[1024];                    // [kx][c]
    __shared__ float ct[256], st[256];
    int tid = threadIdx.x;                         // 256
    int ky = blockIdx.x & 15, yg = (blockIdx.x >> 4) & 15, b = blockIdx.x >> 8;
    {
        float ang = 6.283185307179586f * (float)tid / 256.f;
        ct[tid] = cosf(ang); st[tid] = sinf(ang);
    }
    const float2* src = mixedT + (size_t)(b * 16 + ky) * 1024;
    for (int idx = tid; idx < 1024; idx += 256) sm[idx] = src[idx];
    __syncthreads();
    int c = tid & 63, yl = tid >> 6;
    #pragma unroll
    for (int yi = 0; yi < 4; ++yi){
        int yy = yg * 16 + yl * 4 + yi;
        float re = 0.f, im = 0.f;
        #pragma unroll
        for (int kx = 0; kx < 16; ++kx){
            float2 v = sm[kx * 64 + c];
            int t = (kx * yy) & 255;
            float cc = ct[t], ss = st[t];
            re += v.x * cc - v.y * ss;
            im += v.x * ss + v.y * cc;
        }
        G[((size_t)(b * 256 + yy) * 16 + ky) * 64 + c] = make_float2(re, im);
    }
}

// ---------------- fused: 1x1 conv + inv DFT along W + bias + relu (f32x2) ----------------
// dyn smem: 77056 B
#define CONV1(oo, wv) \
    acc[oo][0] = ffma2(wv, h2.x, acc[oo][0]); \
    acc[oo][1] = ffma2(wv, h2.y, acc[oo][1]);
#define INV1(oo, gx, gy) \
    acc[oo][0] = ffma2(gx, A2v.x, acc[oo][0]); \
    acc[oo][0] = ffma2(gy, B2v.x, acc[oo][0]); \
    acc[oo][1] = ffma2(gx, A2v.y, acc[oo][1]); \
    acc[oo][1] = ffma2(gy, B2v.y, acc[oo][1]);

__global__ __launch_bounds__(256) void kfused(
        const float* __restrict__ hin, const float2* __restrict__ G,
        const float* __restrict__ ww, const float* __restrict__ wb,
        float* __restrict__ hout){
    extern __shared__ __align__(16) u64 dsm2[];
    u64*   swc2 = dsm2;                            // [64][66]  (w,w) [i][o]
    u64*   sgx2 = swc2 + 64 * 66;                  // [16][66]
    u64*   sgy2 = sgx2 + 16 * 66;                  // [16][66]
    float* sh   = (float*)(sgy2 + 16 * 66);        // [64][68]
    float* sA   = sh + 64 * 68;                    // [16][68]
    float* sB   = sA + 16 * 68;                    // [16][68]
    float* sb   = sB + 16 * 68;                    // [64]
    int tid = threadIdx.x;                         // 256
    int xc = (blockIdx.x & 3) << 6;
    int y  = (blockIdx.x >> 2) & 255;
    int b  = blockIdx.x >> 10;

    const float* hb = hin + ((size_t)(b * 64) * 256 + y) * 256 + xc;
    for (int idx = tid; idx < 4096; idx += 256){
        int a = idx >> 6, c = idx & 63;
        sh[a * 68 + c] = hb[(size_t)a * 65536 + c];
        float wv = ww[idx];                        // w[o=a][i=c]
        swc2[c * 66 + a] = fpack2(wv, wv);
    }
    const float2* Gb = G + ((size_t)(b * 256) + y) * 1024;
    for (int idx = tid; idx < 1024; idx += 256){
        int ky = idx >> 6, o = idx & 63;
        float2 g = Gb[ky * 64 + o];
        sgx2[ky * 66 + o] = fpack2(g.x, g.x);
        sgy2[ky * 66 + o] = fpack2(g.y, g.y);
        sA[ky * 68 + o] = g_ic[ky * 256 + xc + o];
        sB[ky * 68 + o] = g_is[ky * 256 + xc + o];
    }
    if (tid < 64) sb[tid] = wb[tid];
    __syncthreads();

    int o0 = (tid >> 4) * 4;
    int x0 = (tid & 15) * 4;
    u64 acc[4][2];
    #pragma unroll
    for (int oo = 0; oo < 4; ++oo){
        float bv = sb[o0 + oo];
        acc[oo][0] = acc[oo][1] = fpack2(bv, bv);
    }
    #pragma unroll 4
    for (int i = 0; i < 64; ++i){
        ulonglong2 h2  = *(const ulonglong2*)&sh[i * 68 + x0];
        ulonglong2 w01 = *(const ulonglong2*)&swc2[i * 66 + o0];
        ulonglong2 w23 = *(const ulonglong2*)&swc2[i * 66 + o0 + 2];
        CONV1(0, w01.x) CONV1(1, w01.y) CONV1(2, w23.x) CONV1(3, w23.y)
    }
    #pragma unroll 4
    for (int ky = 0; ky < 16; ++ky){
        ulonglong2 A2v  = *(const ulonglong2*)&sA[ky * 68 + x0];
        ulonglong2 B2v  = *(const ulonglong2*)&sB[ky * 68 + x0];
        ulonglong2 gx01 = *(const ulonglong2*)&sgx2[ky * 66 + o0];
        ulonglong2 gx23 = *(const ulonglong2*)&sgx2[ky * 66 + o0 + 2];
        ulonglong2 gy01 = *(const ulonglong2*)&sgy2[ky * 66 + o0];
        ulonglong2 gy23 = *(const ulonglong2*)&sgy2[ky * 66 + o0 + 2];
        INV1(0, gx01.x, gy01.x) INV1(1, gx01.y, gy01.y)
        INV1(2, gx23.x, gy23.x) INV1(3, gx23.y, gy23.y)
    }
    float* ob = hout + ((size_t)(b * 64 + o0) * 256 + y) * 256 + xc + x0;
    #pragma unroll
    for (int oo = 0; oo < 4; ++oo){
        float2 p0 = funpack2(acc[oo][0]);
        float2 p1 = funpack2(acc[oo][1]);
        float4 v = make_float4(fmaxf(p0.x, 0.f), fmaxf(p0.y, 0.f),
                               fmaxf(p1.x, 0.f), fmaxf(p1.y, 0.f));
        *(float4*)&ob[(size_t)oo * 65536] = v;
    }
}

// ---------------- fused MLP head (f32x2) ----------------
// dyn smem: 105472 B
#define HSTEP(mp, wv) \
    acch[mp][0] = ffma2(wv, h01.x, acch[mp][0]); \
    acch[mp][1] = ffma2(wv, h01.y, acch[mp][1]); \
    acch[mp][2] = ffma2(wv, h23.x, acch[mp][2]); \
    acch[mp][3] = ffma2(wv, h23.y, acch[mp][3]);

__global__ __launch_bounds__(256) void khead(
        const float* __restrict__ hin,
        const float* __restrict__ w1, const float* __restrict__ b1,
        const float* __restrict__ w2, const float* __restrict__ b2,
        float* __restrict__ out){
    extern __shared__ __align__(16) u64 dsm3[];
    u64*   sh2  = dsm3;                            // [64][68]  (h,h) dup
    float* sw1t = (float*)(sh2 + 64 * 68);         // [64][132] w1^T [c][m]
    float* shid = sw1t + 64 * 132;                 // [128][68]
    float* sw2s = shid + 128 * 68;                 // [384]
    float* sb1s = sw2s + 384;                      // [128]
    int tid = threadIdx.x;                         // 256
    int xc = (blockIdx.x & 3) << 6;
    int y  = (blockIdx.x >> 2) & 255;
    int b  = blockIdx.x >> 10;

    const float* hb = hin + ((size_t)(b * 64) * 256 + y) * 256 + xc;
    for (int idx = tid; idx < 4096; idx += 256){
        int c = idx >> 6, xl = idx & 63;
        float v = hb[(size_t)c * 65536 + xl];
        sh2[c * 68 + xl] = fpack2(v, v);
    }
    for (int idx = tid; idx < 8192; idx += 256){
        int m = idx >> 6, c = idx & 63;
        sw1t[c * 132 + m] = w1[idx];               // w1 [m][c]
    }
    for (int idx = tid; idx < 384; idx += 256) sw2s[idx] = w2[idx];
    if (tid < 128) sb1s[tid] = b1[tid];
    __syncthreads();

    int m0 = (tid >> 4) * 8;
    int x0 = (tid & 15) * 4;
    u64 acch[4][4];
    #pragma unroll
    for (int mp = 0; mp < 4; ++mp){
        float2 bp = *(const float2*)&sb1s[m0 + 2 * mp];
        u64 bb = fpack2(bp.x, bp.y);
        #pragma unroll
        for (int xx = 0; xx < 4; ++xx) acch[mp][xx] = bb;
    }
    #pragma unroll 4
    for (int c = 0; c < 64; ++c){
        ulonglong2 h01 = *(const ulonglong2*)&sh2[c * 68 + x0];
        ulonglong2 h23 = *(const ulonglong2*)&sh2[c * 68 + x0 + 2];
        ulonglong2 wA  = *(const ulonglong2*)&sw1t[c * 132 + m0];
        ulonglong2 wB  = *(const ulonglong2*)&sw1t[c * 132 + m0 + 4];
        HSTEP(0, wA.x) HSTEP(1, wA.y) HSTEP(2, wB.x) HSTEP(3, wB.y)
    }
    #pragma unroll
    for (int mp = 0; mp < 4; ++mp)
        #pragma unroll
        for (int xx = 0; xx < 4; ++xx){
            float2 v = funpack2(acch[mp][xx]);
            shid[(m0 + 2 * mp)     * 68 + x0 + xx] = fmaxf(v.x, 0.f);
            shid[(m0 + 2 * mp + 1) * 68 + x0 + xx] = fmaxf(v.y, 0.f);
        }
    __syncthreads();
    if (tid < 192){
        int o = tid >> 6, xl = tid & 63;
        float a = b2[o];
        #pragma unroll 8
        for (int m = 0; m < 128; ++m)
            a = fmaf(shid[m * 68 + xl], sw2s[o * 128 + m], a);
        out[((size_t)(b * 3 + o) * 256 + y) * 256 + xc + xl] = a;
    }
}

// ---------------- host ----------------
extern "C" void kernel_launch(void* const* d_in, const int* in_sizes, int n_in,
                              void* d_out, int out_size) {
    const float* x       = (const float*)d_in[0];
    const float* fc0_w   = (const float*)d_in[1];
    const float* fc0_b   = (const float*)d_in[2];
    const float* spec_re = (const float*)d_in[3];
    const float* spec_im = (const float*)d_in[4];
    const float* w_w     = (const float*)d_in[5];
    const float* w_b     = (const float*)d_in[6];
    const float* fc1_w   = (const float*)d_in[7];
    const float* fc1_b   = (const float*)d_in[8];
    const float* fc2_w   = (const float*)d_in[9];
    const float* fc2_b   = (const float*)d_in[10];

    float  *h0, *h1;
    float2 *f1, *mo, *mx, *G, *wt;
    cudaGetSymbolAddress((void**)&h0, g_h0);
    cudaGetSymbolAddress((void**)&h1, g_h1);
    cudaGetSymbolAddress((void**)&f1, g_f1);
    cudaGetSymbolAddress((void**)&mo, g_modes);
    cudaGetSymbolAddress((void**)&mx, g_mixed);
    cudaGetSymbolAddress((void**)&G,  g_G);
    cudaGetSymbolAddress((void**)&wt, g_wt);

    cudaFuncSetAttribute(kfwd1,  cudaFuncAttributeMaxDynamicSharedMemorySize, 71680);
    cudaFuncSetAttribute(kfused, cudaFuncAttributeMaxDynamicSharedMemorySize, 77056);
    cudaFuncSetAttribute(khead,  cudaFuncAttributeMaxDynamicSharedMemorySize, 105472);

    kprep<<<16, 256>>>();
    ktw<<<16384, 256>>>(spec_re, spec_im);
    kfc0<<<32768, 256>>>(x, fc0_w, fc0_b, h0);

    float* hin = h0;
    float* hout = h1;
    for (int d = 0; d < NDEPTH; ++d) {
        kfwd1<<<1024, 256, 71680>>>(hin, f1);
        kfwd2<<<512, 512>>>(f1, mo);
        kmix<<<256, 256>>>(mo, wt + (size_t)d * 256 * 4096, mx);
        kinv1<<<2048, 256>>>(mx, G);
        kfused<<<8192, 256, 77056>>>(hin, G, w_w + d * 4096, w_b + d * 64, hout);
        float* t = hin; hin = hout; hout = t;
    }
    khead<<<8192, 256, 105472>>>(hin, fc1_w, fc1_b, fc2_w, fc2_b, (float*)d_out);
}

// round 7
// speedup vs baseline: 1.0171x; 1.0159x over previous
#include <cuda_runtime.h>

#define NDEPTH 4
typedef unsigned long long u64;

__device__ __forceinline__ u64 ffma2(u64 a, u64 b, u64 c){
    u64 d; asm("fma.rn.f32x2 %0, %1, %2, %3;" : "=l"(d) : "l"(a), "l"(b), "l"(c)); return d;
}
__device__ __forceinline__ u64 fpack2(float x, float y){
    u64 d; asm("mov.b64 %0, {%1, %2};" : "=l"(d) : "f"(x), "f"(y)); return d;
}
__device__ __forceinline__ float2 funpack2(u64 a){
    float x, y; asm("mov.b64 {%0, %1}, %2;" : "=f"(x), "=f"(y) : "l"(a)); return make_float2(x, y);
}

// ---------------- scratch (device globals) ----------------
__device__ float  g_h0[8*64*65536];
__device__ float  g_h1[8*64*65536];
__device__ float2 g_f1[8*64*256*16];
__device__ float2 g_modes[8*64*256];
__device__ float2 g_mixed[8*64*256];               // mixedT [b][ky][kx][o]
__device__ float2 g_G[8*256*16*64];                // [b][y][ky][c]
__device__ float2 g_wt[NDEPTH*256*64*64];          // [d][m][i][o]
__device__ float  g_ec[16*256], g_es[16*256];      // fwd: (cos, -sin) split
__device__ float  g_ic[16*256], g_is[16*256];      // inv-W scaled tables

// ---------------- prep: DFT tables ----------------
__global__ void kprep(){
    int idx = blockIdx.x * 256 + threadIdx.x;      // 4096 = [ky][x]
    int x = idx & 255, ky = idx >> 8;
    float ang = 6.283185307179586f * (float)((ky * x) & 255) / 256.f;
    float c = cosf(ang), s = sinf(ang);
    g_ec[idx] = c; g_es[idx] = -s;
    const float sc = 1.f / 65536.f;
    g_ic[idx] = (ky == 0) ? sc : 2.f * sc * c;
    g_is[idx] = (ky == 0) ? 0.f : -2.f * sc * s;
}

// ---------------- spectral weight transpose: [d][i][o][kx][ky] -> [d][m][i][o] ----------------
__global__ void ktw(const float* __restrict__ wre, const float* __restrict__ wim){
    int idx = blockIdx.x * 256 + threadIdx.x;
    int ky = idx & 15, kx = (idx >> 4) & 15, o = (idx >> 8) & 63, i = (idx >> 14) & 63, d = idx >> 20;
    int m = kx * 16 + ky;
    g_wt[((d * 256 + m) * 64 + i) * 64 + o] = make_float2(wre[idx], wim[idx]);
}

// ---------------- fc0: 3 -> 64 channels, float4 ----------------
__global__ void kfc0(const float* __restrict__ x, const float* __restrict__ w,
                     const float* __restrict__ bv, float* __restrict__ out){
    int idx = blockIdx.x * 256 + threadIdx.x;      // 8*64*16384
    int p4 = idx & 16383;
    int c  = (idx >> 14) & 63;
    int b  = idx >> 20;
    const float* xb = x + (size_t)b * 3 * 65536 + p4 * 4;
    float4 a0 = *(const float4*)&xb[0];
    float4 a1 = *(const float4*)&xb[65536];
    float4 a2 = *(const float4*)&xb[131072];
    float w0 = w[c*3], w1 = w[c*3+1], w2 = w[c*3+2], bb = bv[c];
    float4 r;
    r.x = bb + a0.x*w0 + a1.x*w1 + a2.x*w2;
    r.y = bb + a0.y*w0 + a1.y*w1 + a2.y*w2;
    r.z = bb + a0.z*w0 + a1.z*w1 + a2.z*w2;
    r.w = bb + a0.w*w0 + a1.w*w1 + a2.w*w2;
    *(float4*)&out[(size_t)idx * 4] = r;
}

// ---------------- fwd DFT along W (256 -> 16 modes), f32x2 register-blocked ----------------
// block: 128 rows, 256 threads, thread tile 2 rows x 4 ky (re,im packed)
__global__ void kfwd1(const float* __restrict__ hin, float2* __restrict__ f1){
    extern __shared__ __align__(16) u64 dsm1[];
    u64* sh2 = dsm1;                               // [128][34]  (h,h) dup per x chunk
    u64* tcs = dsm1 + 128 * 34;                    // [256][18]  (cos,-sin)
    int tid = threadIdx.x;                         // 256
    size_t rowbase = (size_t)blockIdx.x * 128;
    for (int idx = tid; idx < 4096; idx += 256){
        int ky = idx & 15, x = idx >> 4;
        tcs[x * 18 + ky] = fpack2(g_ec[ky * 256 + x], g_es[ky * 256 + x]);
    }
    int r0 = (tid >> 2) * 2;
    int k0 = (tid & 3) * 4;
    u64 acc[2][4];
    #pragma unroll
    for (int a = 0; a < 2; ++a)
        #pragma unroll
        for (int k = 0; k < 4; ++k) acc[a][k] = 0ull;

    for (int ch = 0; ch < 8; ++ch){
        int xb = ch * 32;
        __syncthreads();
        for (int idx = tid; idx < 1024; idx += 256){
            int r = idx >> 3, xq = (idx & 7) * 4;
            float4 v = *(const float4*)&hin[(rowbase + r) * 256 + xb + xq];
            u64* dst = &sh2[r * 34 + xq];
            dst[0] = fpack2(v.x, v.x);
            dst[1] = fpack2(v.y, v.y);
            dst[2] = fpack2(v.z, v.z);
            dst[3] = fpack2(v.w, v.w);
        }
        __syncthreads();
        #pragma unroll 4
        for (int xl = 0; xl < 32; ++xl){
            int x = xb + xl;
            u64 h0 = sh2[r0 * 34 + xl];
            u64 h1 = sh2[(r0 + 1) * 34 + xl];
            ulonglong2 t0 = *(const ulonglong2*)&tcs[x * 18 + k0];
            ulonglong2 t1 = *(const ulonglong2*)&tcs[x * 18 + k0 + 2];
            acc[0][0] = ffma2(h0, t0.x, acc[0][0]);
            acc[0][1] = ffma2(h0, t0.y, acc[0][1]);
            acc[0][2] = ffma2(h0, t1.x, acc[0][2]);
            acc[0][3] = ffma2(h0, t1.y, acc[0][3]);
            acc[1][0] = ffma2(h1, t0.x, acc[1][0]);
            acc[1][1] = ffma2(h1, t0.y, acc[1][1]);
            acc[1][2] = ffma2(h1, t1.x, acc[1][2]);
            acc[1][3] = ffma2(h1, t1.y, acc[1][3]);
        }
    }
    #pragma unroll
    for (int a = 0; a < 2; ++a)
        #pragma unroll
        for (int k = 0; k < 4; ++k)
            f1[(rowbase + r0 + a) * 16 + k0 + k] = funpack2(acc[a][k]);
}

// ---------------- fwd DFT along H (256 -> 16 modes), split-K ----------------
__global__ void kfwd2(const float2* __restrict__ f1, float2* __restrict__ modes){
    __shared__ float2 sf[4096];
    __shared__ float ct[256], st[256];
    __shared__ float2 sred[256];
    int tid = threadIdx.x;                         // 512
    if (tid < 256){
        float ang = 6.283185307179586f * (float)tid / 256.f;
        ct[tid] = cosf(ang); st[tid] = sinf(ang);
    }
    int bc = blockIdx.x;
    const float2* src = f1 + (size_t)bc * 4096;
    for (int idx = tid; idx < 4096; idx += 512) sf[idx] = src[idx];
    __syncthreads();
    int outi = tid & 255;
    int kx = outi >> 4, ky = outi & 15;
    int yb = (tid >> 8) * 128;
    float re = 0.f, im = 0.f;
    #pragma unroll 8
    for (int yy = yb; yy < yb + 128; ++yy){
        float2 v = sf[yy * 16 + ky];
        int t = (kx * yy) & 255;
        float c = ct[t], s = st[t];
        re += v.x * c + v.y * s;
        im += v.y * c - v.x * s;
    }
    if (tid >= 256) sred[outi] = make_float2(re, im);
    __syncthreads();
    if (tid < 256){
        float2 o = sred[outi];
        modes[bc * 256 + outi] = make_float2(re + o.x, im + o.y);
    }
}

// ---------------- mode mixing -> mixedT [b][ky][kx][o] ----------------
__global__ void kmix(const float2* __restrict__ modes, const float2* __restrict__ wt,
                     float2* __restrict__ mixedT){
    __shared__ float2 swt[4096];
    __shared__ float2 sin_[512];
    int tid = threadIdx.x, m = blockIdx.x;
    int ky = m & 15, kx = m >> 4;
    const float2* wsrc = wt + (size_t)m * 4096;
    for (int idx = tid; idx < 4096; idx += 256) swt[idx] = wsrc[idx];
    for (int idx = tid; idx < 512; idx += 256){
        int b = idx >> 6, i = idx & 63;
        sin_[idx] = modes[(b * 64 + i) * 256 + m];
    }
    __syncthreads();
    int o = tid & 63;
    for (int half = 0; half < 2; ++half){
        int b = (tid >> 6) + half * 4;
        float re = 0.f, im = 0.f;
        #pragma unroll 8
        for (int i = 0; i < 64; ++i){
            float2 a = sin_[b * 64 + i];
            float2 wv = swt[i * 64 + o];
            re += a.x * wv.x - a.y * wv.y;
            im += a.x * wv.y + a.y * wv.x;
        }
        mixedT[((b * 16 + ky) * 16 + kx) * 64 + o] = make_float2(re, im);
    }
}

// ---------------- inv DFT along H (16 -> 256): G [b][y][ky][c] ----------------
__global__ void kinv1(const float2* __restrict__ mixedT, float2* __restrict__ G){
    __shared__ float2 sm[1024];                    // [kx][c]
    __shared__ float ct[256], st[256];
    int tid = threadIdx.x;                         // 256
    int ky = blockIdx.x & 15, yg = (blockIdx.x >> 4) & 15, b = blockIdx.x >> 8;
    {
        float ang = 6.283185307179586f * (float)tid / 256.f;
        ct[tid] = cosf(ang); st[tid] = sinf(ang);
    }
    const float2* src = mixedT + (size_t)(b * 16 + ky) * 1024;
    for (int idx = tid; idx < 1024; idx += 256) sm[idx] = src[idx];
    __syncthreads();
    int c = tid & 63, yl = tid >> 6;
    #pragma unroll
    for (int yi = 0; yi < 4; ++yi){
        int yy = yg * 16 + yl * 4 + yi;
        float re = 0.f, im = 0.f;
        #pragma unroll
        for (int kx = 0; kx < 16; ++kx){
            float2 v = sm[kx * 64 + c];
            int t = (kx * yy) & 255;
            float cc = ct[t], ss = st[t];
            re += v.x * cc - v.y * ss;
            im += v.x * ss + v.y * cc;
        }
        G[((size_t)(b * 256 + yy) * 16 + ky) * 64 + c] = make_float2(re, im);
    }
}

// ---------------- fused: 1x1 conv + inv DFT along W + bias + relu (f32x2) ----------------
// dyn smem: 77056 B
#define CONV1(oo, wv) \
    acc[oo][0] = ffma2(wv, h2.x, acc[oo][0]); \
    acc[oo][1] = ffma2(wv, h2.y, acc[oo][1]);
#define INV1(oo, gx, gy) \
    acc[oo][0] = ffma2(gx, A2v.x, acc[oo][0]); \
    acc[oo][0] = ffma2(gy, B2v.x, acc[oo][0]); \
    acc[oo][1] = ffma2(gx, A2v.y, acc[oo][1]); \
    acc[oo][1] = ffma2(gy, B2v.y, acc[oo][1]);

__global__ __launch_bounds__(256) void kfused(
        const float* __restrict__ hin, const float2* __restrict__ G,
        const float* __restrict__ ww, const float* __restrict__ wb,
        float* __restrict__ hout){
    extern __shared__ __align__(16) u64 dsm2[];
    u64*   swc2 = dsm2;                            // [64][66]  (w,w) [i][o]
    u64*   sgx2 = swc2 + 64 * 66;                  // [16][66]
    u64*   sgy2 = sgx2 + 16 * 66;                  // [16][66]
    float* sh   = (float*)(sgy2 + 16 * 66);        // [64][68]
    float* sA   = sh + 64 * 68;                    // [16][68]
    float* sB   = sA + 16 * 68;                    // [16][68]
    float* sb   = sB + 16 * 68;                    // [64]
    int tid = threadIdx.x;                         // 256
    int xc = (blockIdx.x & 3) << 6;
    int y  = (blockIdx.x >> 2) & 255;
    int b  = blockIdx.x >> 10;

    const float* hb = hin + ((size_t)(b * 64) * 256 + y) * 256 + xc;
    for (int idx = tid; idx < 4096; idx += 256){
        int a = idx >> 6, c = idx & 63;
        sh[a * 68 + c] = hb[(size_t)a * 65536 + c];
        float wv = ww[idx];                        // w[o=a][i=c]
        swc2[c * 66 + a] = fpack2(wv, wv);
    }
    const float2* Gb = G + ((size_t)(b * 256) + y) * 1024;
    for (int idx = tid; idx < 1024; idx += 256){
        int ky = idx >> 6, o = idx & 63;
        float2 g = Gb[ky * 64 + o];
        sgx2[ky * 66 + o] = fpack2(g.x, g.x);
        sgy2[ky * 66 + o] = fpack2(g.y, g.y);
        sA[ky * 68 + o] = g_ic[ky * 256 + xc + o];
        sB[ky * 68 + o] = g_is[ky * 256 + xc + o];
    }
    if (tid < 64) sb[tid] = wb[tid];
    __syncthreads();

    int o0 = (tid >> 4) * 4;
    int x0 = (tid & 15) * 4;
    u64 acc[4][2];
    #pragma unroll
    for (int oo = 0; oo < 4; ++oo){
        float bv = sb[o0 + oo];
        acc[oo][0] = acc[oo][1] = fpack2(bv, bv);
    }
    #pragma unroll 4
    for (int i = 0; i < 64; ++i){
        ulonglong2 h2  = *(const ulonglong2*)&sh[i * 68 + x0];
        ulonglong2 w01 = *(const ulonglong2*)&swc2[i * 66 + o0];
        ulonglong2 w23 = *(const ulonglong2*)&swc2[i * 66 + o0 + 2];
        CONV1(0, w01.x) CONV1(1, w01.y) CONV1(2, w23.x) CONV1(3, w23.y)
    }
    #pragma unroll 4
    for (int ky = 0; ky < 16; ++ky){
        ulonglong2 A2v  = *(const ulonglong2*)&sA[ky * 68 + x0];
        ulonglong2 B2v  = *(const ulonglong2*)&sB[ky * 68 + x0];
        ulonglong2 gx01 = *(const ulonglong2*)&sgx2[ky * 66 + o0];
        ulonglong2 gx23 = *(const ulonglong2*)&sgx2[ky * 66 + o0 + 2];
        ulonglong2 gy01 = *(const ulonglong2*)&sgy2[ky * 66 + o0];
        ulonglong2 gy23 = *(const ulonglong2*)&sgy2[ky * 66 + o0 + 2];
        INV1(0, gx01.x, gy01.x) INV1(1, gx01.y, gy01.y)
        INV1(2, gx23.x, gy23.x) INV1(3, gx23.y, gy23.y)
    }
    float* ob = hout + ((size_t)(b * 64 + o0) * 256 + y) * 256 + xc + x0;
    #pragma unroll
    for (int oo = 0; oo < 4; ++oo){
        float2 p0 = funpack2(acc[oo][0]);
        float2 p1 = funpack2(acc[oo][1]);
        float4 v = make_float4(fmaxf(p0.x, 0.f), fmaxf(p0.y, 0.f),
                               fmaxf(p1.x, 0.f), fmaxf(p1.y, 0.f));
        *(float4*)&ob[(size_t)oo * 65536] = v;
    }
}

// ---------------- fused MLP head (f32x2) ----------------
// dyn smem: 105472 B
#define HSTEP(mp, wv) \
    acch[mp][0] = ffma2(wv, h01.x, acch[mp][0]); \
    acch[mp][1] = ffma2(wv, h01.y, acch[mp][1]); \
    acch[mp][2] = ffma2(wv, h23.x, acch[mp][2]); \
    acch[mp][3] = ffma2(wv, h23.y, acch[mp][3]);

__global__ __launch_bounds__(256) void khead(
        const float* __restrict__ hin,
        const float* __restrict__ w1, const float* __restrict__ b1,
        const float* __restrict__ w2, const float* __restrict__ b2,
        float* __restrict__ out){
    extern __shared__ __align__(16) u64 dsm3[];
    u64*   sh2  = dsm3;                            // [64][68]  (h,h) dup
    float* sw1t = (float*)(sh2 + 64 * 68);         // [64][132] w1^T [c][m]
    float* shid = sw1t + 64 * 132;                 // [128][68]
    float* sw2s = shid + 128 * 68;                 // [384]
    float* sb1s = sw2s + 384;                      // [128]
    int tid = threadIdx.x;                         // 256
    int xc = (blockIdx.x & 3) << 6;
    int y  = (blockIdx.x >> 2) & 255;
    int b  = blockIdx.x >> 10;

    const float* hb = hin + ((size_t)(b * 64) * 256 + y) * 256 + xc;
    for (int idx = tid; idx < 4096; idx += 256){
        int c = idx >> 6, xl = idx & 63;
        float v = hb[(size_t)c * 65536 + xl];
        sh2[c * 68 + xl] = fpack2(v, v);
    }
    for (int idx = tid; idx < 8192; idx += 256){
        int m = idx >> 6, c = idx & 63;
        sw1t[c * 132 + m] = w1[idx];               // w1 [m][c]
    }
    for (int idx = tid; idx < 384; idx += 256) sw2s[idx] = w2[idx];
    if (tid < 128) sb1s[tid] = b1[tid];
    __syncthreads();

    int m0 = (tid >> 4) * 8;
    int x0 = (tid & 15) * 4;
    u64 acch[4][4];
    #pragma unroll
    for (int mp = 0; mp < 4; ++mp){
        float2 bp = *(const float2*)&sb1s[m0 + 2 * mp];
        u64 bb = fpack2(bp.x, bp.y);
        #pragma unroll
        for (int xx = 0; xx < 4; ++xx) acch[mp][xx] = bb;
    }
    #pragma unroll 4
    for (int c = 0; c < 64; ++c){
        ulonglong2 h01 = *(const ulonglong2*)&sh2[c * 68 + x0];
        ulonglong2 h23 = *(const ulonglong2*)&sh2[c * 68 + x0 + 2];
        ulonglong2 wA  = *(const ulonglong2*)&sw1t[c * 132 + m0];
        ulonglong2 wB  = *(const ulonglong2*)&sw1t[c * 132 + m0 + 4];
        HSTEP(0, wA.x) HSTEP(1, wA.y) HSTEP(2, wB.x) HSTEP(3, wB.y)
    }
    #pragma unroll
    for (int mp = 0; mp < 4; ++mp)
        #pragma unroll
        for (int xx = 0; xx < 4; ++xx){
            float2 v = funpack2(acch[mp][xx]);
            shid[(m0 + 2 * mp)     * 68 + x0 + xx] = fmaxf(v.x, 0.f);
            shid[(m0 + 2 * mp + 1) * 68 + x0 + xx] = fmaxf(v.y, 0.f);
        }
    __syncthreads();
    if (tid < 192){
        int o = tid >> 6, xl = tid & 63;
        float a = b2[o];
        #pragma unroll 8
        for (int m = 0; m < 128; ++m)
            a = fmaf(shid[m * 68 + xl], sw2s[o * 128 + m], a);
        out[((size_t)(b * 3 + o) * 256 + y) * 256 + xc + xl] = a;
    }
}

// ---------------- host ----------------
extern "C" void kernel_launch(void* const* d_in, const int* in_sizes, int n_in,
                              void* d_out, int out_size) {
    const float* x       = (const float*)d_in[0];
    const float* fc0_w   = (const float*)d_in[1];
    const float* fc0_b   = (const float*)d_in[2];
    const float* spec_re = (const float*)d_in[3];
    const float* spec_im = (const float*)d_in[4];
    const float* w_w     = (const float*)d_in[5];
    const float* w_b     = (const float*)d_in[6];
    const float* fc1_w   = (const float*)d_in[7];
    const float* fc1_b   = (const float*)d_in[8];
    const float* fc2_w   = (const float*)d_in[9];
    const float* fc2_b   = (const float*)d_in[10];

    float  *h0, *h1;
    float2 *f1, *mo, *mx, *G, *wt;
    cudaGetSymbolAddress((void**)&h0, g_h0);
    cudaGetSymbolAddress((void**)&h1, g_h1);
    cudaGetSymbolAddress((void**)&f1, g_f1);
    cudaGetSymbolAddress((void**)&mo, g_modes);
    cudaGetSymbolAddress((void**)&mx, g_mixed);
    cudaGetSymbolAddress((void**)&G,  g_G);
    cudaGetSymbolAddress((void**)&wt, g_wt);

    cudaFuncSetAttribute(kfwd1,  cudaFuncAttributeMaxDynamicSharedMemorySize, 71680);
    cudaFuncSetAttribute(kfused, cudaFuncAttributeMaxDynamicSharedMemorySize, 77056);
    cudaFuncSetAttribute(khead,  cudaFuncAttributeMaxDynamicSharedMemorySize, 105472);

    kprep<<<16, 256>>>();
    ktw<<<16384, 256>>>(spec_re, spec_im);
    kfc0<<<32768, 256>>>(x, fc0_w, fc0_b, h0);

    float* hin = h0;
    float* hout = h1;
    for (int d = 0; d < NDEPTH; ++d) {
        kfwd1<<<1024, 256, 71680>>>(hin, f1);
        kfwd2<<<512, 512>>>(f1, mo);
        kmix<<<256, 256>>>(mo, wt + (size_t)d * 256 * 4096, mx);
        kinv1<<<2048, 256>>>(mx, G);
        kfused<<<8192, 256, 77056>>>(hin, G, w_w + d * 4096, w_b + d * 64, hout);
        float* t = hin; hin = hout; hout = t;
    }
    khead<<<8192, 256, 105472>>>(hin, fc1_w, fc1_b, fc2_w, fc2_b, (float*)d_out);
}

// round 8
// speedup vs baseline: 2.0807x; 2.0457x over previous
#include <cuda_runtime.h>

#define NDEPTH 4
typedef unsigned long long u64;

__device__ __forceinline__ u64 ffma2(u64 a, u64 b, u64 c){
    u64 d; asm("fma.rn.f32x2 %0, %1, %2, %3;" : "=l"(d) : "l"(a), "l"(b), "l"(c)); return d;
}
__device__ __forceinline__ u64 fpack2(float x, float y){
    u64 d; asm("mov.b64 %0, {%1, %2};" : "=l"(d) : "f"(x), "f"(y)); return d;
}
__device__ __forceinline__ float2 funpack2(u64 a){
    float x, y; asm("mov.b64 {%0, %1}, %2;" : "=f"(x), "=f"(y) : "l"(a)); return make_float2(x, y);
}

// ---------------- scratch (device globals) ----------------
__device__ float  g_h0[8*64*65536];
__device__ float  g_h1[8*64*65536];
__device__ float2 g_f1[8*64*256*16];
__device__ float2 g_modes[8*64*256];
__device__ float2 g_mixed[8*64*256];               // mixedT [b][ky][kx][o]
__device__ float2 g_G[8*256*16*64];                // [b][y][ky][c]
__device__ float2 g_wt[NDEPTH*256*64*64];          // [d][m][i][o]
__device__ float  g_ec[16*256], g_es[16*256];      // fwd: (cos, -sin)
__device__ float  g_ic[16*256], g_is[16*256];      // inv-W scaled tables

// ---------------- prep: DFT tables ----------------
__global__ void kprep(){
    int idx = blockIdx.x * 256 + threadIdx.x;      // 4096 = [ky][x]
    int x = idx & 255, ky = idx >> 8;
    float ang = 6.283185307179586f * (float)((ky * x) & 255) / 256.f;
    float c = cosf(ang), s = sinf(ang);
    g_ec[idx] = c; g_es[idx] = -s;
    const float sc = 1.f / 65536.f;
    g_ic[idx] = (ky == 0) ? sc : 2.f * sc * c;
    g_is[idx] = (ky == 0) ? 0.f : -2.f * sc * s;
}

// ---------------- spectral weight transpose ----------------
__global__ void ktw(const float* __restrict__ wre, const float* __restrict__ wim){
    int idx = blockIdx.x * 256 + threadIdx.x;
    int ky = idx & 15, kx = (idx >> 4) & 15, o = (idx >> 8) & 63, i = (idx >> 14) & 63, d = idx >> 20;
    int m = kx * 16 + ky;
    g_wt[((d * 256 + m) * 64 + i) * 64 + o] = make_float2(wre[idx], wim[idx]);
}

// ---------------- fc0 ----------------
__global__ void kfc0(const float* __restrict__ x, const float* __restrict__ w,
                     const float* __restrict__ bv, float* __restrict__ out){
    int idx = blockIdx.x * 256 + threadIdx.x;
    int p4 = idx & 16383;
    int c  = (idx >> 14) & 63;
    int b  = idx >> 20;
    const float* xb = x + (size_t)b * 3 * 65536 + p4 * 4;
    float4 a0 = *(const float4*)&xb[0];
    float4 a1 = *(const float4*)&xb[65536];
    float4 a2 = *(const float4*)&xb[131072];
    float w0 = w[c*3], w1 = w[c*3+1], w2 = w[c*3+2], bb = bv[c];
    float4 r;
    r.x = bb + a0.x*w0 + a1.x*w1 + a2.x*w2;
    r.y = bb + a0.y*w0 + a1.y*w1 + a2.y*w2;
    r.z = bb + a0.z*w0 + a1.z*w1 + a2.z*w2;
    r.w = bb + a0.w*w0 + a1.w*w1 + a2.w*w2;
    *(float4*)&out[(size_t)idx * 4] = r;
}

// ---------------- fwd DFT along W: 256 rows/block, thread = 4 rows x 4 ky ----------------
// smem: sh [32 x][260] transposed+XOR-swizzled rows; tw [256 x][16 ky] u64 (c,-s)
__global__ __launch_bounds__(256) void kfwd1(const float* __restrict__ hin, float2* __restrict__ f1){
    extern __shared__ __align__(16) float dsm1[];
    float* sh = dsm1;                               // 32*260 floats
    u64*   tw = (u64*)(dsm1 + 32*260);              // 4096 u64
    int tid = threadIdx.x;
    size_t rowbase = (size_t)blockIdx.x * 256;
    for (int idx = tid; idx < 4096; idx += 256){
        int ky = idx & 15, x = idx >> 4;
        tw[x*16 + ky] = fpack2(g_ec[ky*256 + x], g_es[ky*256 + x]);
    }
    int w = tid >> 5, l = tid & 31;
    int r0 = w*32 + (l >> 2)*4;
    int k0 = (l & 3)*4;
    u64 acc[4][4];
    #pragma unroll
    for (int j = 0; j < 4; ++j)
        #pragma unroll
        for (int k = 0; k < 4; ++k) acc[j][k] = 0ull;

    for (int ch = 0; ch < 8; ++ch){
        int xb = ch * 32;
        __syncthreads();
        #pragma unroll
        for (int k = 0; k < 8; ++k){
            int idx = tid + k*256;
            int r = idx >> 3, xq = (idx & 7)*4;
            float4 g = *(const float4*)&hin[(rowbase + r)*256 + xb + xq];
            sh[(xq+0)*260 + (r ^ ((xq+0)&28))] = g.x;
            sh[(xq+1)*260 + (r ^ ((xq+1)&28))] = g.y;
            sh[(xq+2)*260 + (r ^ ((xq+2)&28))] = g.z;
            sh[(xq+3)*260 + (r ^ ((xq+3)&28))] = g.w;
        }
        __syncthreads();
        #pragma unroll 8
        for (int xl = 0; xl < 32; ++xl){
            float4 h4 = *(const float4*)&sh[xl*260 + (r0 ^ (xl & 28))];
            ulonglong2 t01 = *(const ulonglong2*)&tw[(xb+xl)*16 + k0];
            ulonglong2 t23 = *(const ulonglong2*)&tw[(xb+xl)*16 + k0 + 2];
            u64 h0 = fpack2(h4.x, h4.x), h1 = fpack2(h4.y, h4.y);
            u64 h2 = fpack2(h4.z, h4.z), h3 = fpack2(h4.w, h4.w);
            acc[0][0]=ffma2(h0,t01.x,acc[0][0]); acc[0][1]=ffma2(h0,t01.y,acc[0][1]);
            acc[0][2]=ffma2(h0,t23.x,acc[0][2]); acc[0][3]=ffma2(h0,t23.y,acc[0][3]);
            acc[1][0]=ffma2(h1,t01.x,acc[1][0]); acc[1][1]=ffma2(h1,t01.y,acc[1][1]);
            acc[1][2]=ffma2(h1,t23.x,acc[1][2]); acc[1][3]=ffma2(h1,t23.y,acc[1][3]);
            acc[2][0]=ffma2(h2,t01.x,acc[2][0]); acc[2][1]=ffma2(h2,t01.y,acc[2][1]);
            acc[2][2]=ffma2(h2,t23.x,acc[2][2]); acc[2][3]=ffma2(h2,t23.y,acc[2][3]);
            acc[3][0]=ffma2(h3,t01.x,acc[3][0]); acc[3][1]=ffma2(h3,t01.y,acc[3][1]);
            acc[3][2]=ffma2(h3,t23.x,acc[3][2]); acc[3][3]=ffma2(h3,t23.y,acc[3][3]);
        }
    }
    #pragma unroll
    for (int j = 0; j < 4; ++j){
        size_t base = (rowbase + r0 + j)*16 + k0;
        ulonglong2 v0; v0.x = acc[j][0]; v0.y = acc[j][1];
        ulonglong2 v1; v1.x = acc[j][2]; v1.y = acc[j][3];
        *(ulonglong2*)&f1[base]     = v0;
        *(ulonglong2*)&f1[base + 2] = v1;
    }
}

// ---------------- fwd DFT along H, split-K, 4 partial acc chains ----------------
__global__ void kfwd2(const float2* __restrict__ f1, float2* __restrict__ modes){
    __shared__ float2 sf[4096];
    __shared__ float ct[256], st[256];
    __shared__ float2 sred[256];
    int tid = threadIdx.x;                         // 512
    if (tid < 256){
        float ang = 6.283185307179586f * (float)tid / 256.f;
        ct[tid] = cosf(ang); st[tid] = sinf(ang);
    }
    int bc = blockIdx.x;
    const float2* src = f1 + (size_t)bc * 4096;
    for (int idx = tid; idx < 4096; idx += 512) sf[idx] = src[idx];
    __syncthreads();
    int outi = tid & 255;
    int kx = outi >> 4, ky = outi & 15;
    int yb = (tid >> 8) * 128;
    float re0=0.f, im0=0.f, re1=0.f, im1=0.f;
    #pragma unroll 4
    for (int yy = yb; yy < yb + 128; yy += 2){
        float2 v0 = sf[yy*16 + ky];
        int t0 = (kx * yy) & 255;
        float c0 = ct[t0], s0 = st[t0];
        re0 += v0.x*c0 + v0.y*s0;
        im0 += v0.y*c0 - v0.x*s0;
        float2 v1 = sf[(yy+1)*16 + ky];
        int t1 = (kx * (yy+1)) & 255;
        float c1 = ct[t1], s1 = st[t1];
        re1 += v1.x*c1 + v1.y*s1;
        im1 += v1.y*c1 - v1.x*s1;
    }
    float re = re0 + re1, im = im0 + im1;
    if (tid >= 256) sred[outi] = make_float2(re, im);
    __syncthreads();
    if (tid < 256){
        float2 o = sred[outi];
        modes[bc*256 + outi] = make_float2(re + o.x, im + o.y);
    }
}

// ---------------- mode mixing -> mixedT [b][ky][kx][o] ----------------
__global__ void kmix(const float2* __restrict__ modes, const float2* __restrict__ wt,
                     float2* __restrict__ mixedT){
    __shared__ float2 swt[4096];
    __shared__ float2 sin_[512];
    int tid = threadIdx.x, m = blockIdx.x;
    int ky = m & 15, kx = m >> 4;
    const float2* wsrc = wt + (size_t)m * 4096;
    for (int idx = tid; idx < 4096; idx += 256) swt[idx] = wsrc[idx];
    for (int idx = tid; idx < 512; idx += 256){
        int b = idx >> 6, i = idx & 63;
        sin_[idx] = modes[(b*64 + i)*256 + m];
    }
    __syncthreads();
    int o = tid & 63;
    for (int half = 0; half < 2; ++half){
        int b = (tid >> 6) + half * 4;
        float re = 0.f, im = 0.f;
        #pragma unroll 8
        for (int i = 0; i < 64; ++i){
            float2 a = sin_[b*64 + i];
            float2 wv = swt[i*64 + o];
            re += a.x*wv.x - a.y*wv.y;
            im += a.x*wv.y + a.y*wv.x;
        }
        mixedT[((b*16 + ky)*16 + kx)*64 + o] = make_float2(re, im);
    }
}

// ---------------- inv DFT along H: G [b][y][ky][c] ----------------
__global__ void kinv1(const float2* __restrict__ mixedT, float2* __restrict__ G){
    __shared__ float2 sm[1024];
    __shared__ float ct[256], st[256];
    int tid = threadIdx.x;                         // 256
    int ky = blockIdx.x & 15, yg = (blockIdx.x >> 4) & 15, b = blockIdx.x >> 8;
    {
        float ang = 6.283185307179586f * (float)tid / 256.f;
        ct[tid] = cosf(ang); st[tid] = sinf(ang);
    }
    const float2* src = mixedT + (size_t)(b*16 + ky) * 1024;
    for (int idx = tid; idx < 1024; idx += 256) sm[idx] = src[idx];
    __syncthreads();
    int c = tid & 63, yl = tid >> 6;
    #pragma unroll
    for (int yi = 0; yi < 4; ++yi){
        int yy = yg*16 + yl*4 + yi;
        float re = 0.f, im = 0.f;
        #pragma unroll
        for (int kx = 0; kx < 16; ++kx){
            float2 v = sm[kx*64 + c];
            int t = (kx * yy) & 255;
            float cc = ct[t], ss = st[t];
            re += v.x*cc - v.y*ss;
            im += v.x*ss + v.y*cc;
        }
        G[((size_t)(b*256 + yy)*16 + ky)*64 + c] = make_float2(re, im);
    }
}

// ---------------- fused: 1x1 conv + inv DFT along W + bias + relu ----------------
// block tile 64o x 128x; thread 4o x 8x; smem 76288 B
#define CMAD(oo, wd) \
    acc[oo][0]=ffma2(wd,h01.x,acc[oo][0]); acc[oo][1]=ffma2(wd,h01.y,acc[oo][1]); \
    acc[oo][2]=ffma2(wd,h23.x,acc[oo][2]); acc[oo][3]=ffma2(wd,h23.y,acc[oo][3]);
#define IMAD2(oo, gxd, gyd) \
    acc[oo][0]=ffma2(gxd,A01.x,acc[oo][0]); acc[oo][0]=ffma2(gyd,B01.x,acc[oo][0]); \
    acc[oo][1]=ffma2(gxd,A01.y,acc[oo][1]); acc[oo][1]=ffma2(gyd,B01.y,acc[oo][1]); \
    acc[oo][2]=ffma2(gxd,A23.x,acc[oo][2]); acc[oo][2]=ffma2(gyd,B23.x,acc[oo][2]); \
    acc[oo][3]=ffma2(gxd,A23.y,acc[oo][3]); acc[oo][3]=ffma2(gyd,B23.y,acc[oo][3]);

__global__ __launch_bounds__(256) void kfused(
        const float* __restrict__ hin, const float2* __restrict__ G,
        const float* __restrict__ ww, const float* __restrict__ wb,
        float* __restrict__ hout){
    extern __shared__ __align__(16) float dsm2[];
    float*  sh = dsm2;                             // [64 i][132]
    float*  sA = sh + 64*132;                      // [16 ky][132]
    float*  sB = sA + 16*132;                      // [16 ky][132]
    float*  sw = sB + 16*132;                      // [64 i][66]  w[i][o]
    float2* sg = (float2*)(sw + 64*66);            // [16 ky][66] (gx,gy)
    float*  sb = (float*)(sg + 16*66);             // [64]
    int tid = threadIdx.x;                         // 256
    int xh = blockIdx.x & 1;
    int y  = (blockIdx.x >> 1) & 255;
    int b  = blockIdx.x >> 9;
    int xg2 = xh * 128;

    const float* hb = hin + ((size_t)(b*64)*256 + y)*256 + xg2;
    for (int k = 0; k < 8; ++k){
        int idx = tid + k*256;                     // 2048 float4
        int i = idx >> 5, xq = (idx & 31)*4;
        *(float4*)&sh[i*132 + xq] = *(const float4*)&hb[(size_t)i*65536 + xq];
    }
    for (int k = 0; k < 2; ++k){
        int idx = tid + k*256;                     // 512 float4 = sA,sB
        int ky = idx >> 5, xq = (idx & 31)*4;
        if (ky < 16){
            *(float4*)&sA[ky*132 + xq] = *(const float4*)&g_ic[ky*256 + xg2 + xq];
            *(float4*)&sB[ky*132 + xq] = *(const float4*)&g_is[ky*256 + xg2 + xq];
        }
    }
    for (int k = 0; k < 16; ++k){
        int idx = tid + k*256;                     // 4096: sw[i][o] = ww[o][i]
        int i = idx & 63, o = idx >> 6;
        sw[i*66 + o] = ww[idx];
    }
    {
        const float2* Gb = G + ((size_t)(b*256) + y) * 1024;
        for (int k = 0; k < 4; ++k){
            int idx = tid + k*256;                 // 1024
            int ky = idx >> 6, o = idx & 63;
            sg[ky*66 + o] = Gb[ky*64 + o];
        }
    }
    if (tid < 64) sb[tid] = wb[tid];
    __syncthreads();

    int w = tid >> 5, l = tid & 31;
    int o0 = ((w & 1)*8 + (l >> 2)) * 4;           // 16 o-groups
    int x0 = ((w >> 1)*4 + (l & 3)) * 8;           // 16 x-groups
    u64 acc[4][4];
    {
        float4 bv = *(const float4*)&sb[o0];
        u64 b0 = fpack2(bv.x, bv.x), b1 = fpack2(bv.y, bv.y);
        u64 b2 = fpack2(bv.z, bv.z), b3 = fpack2(bv.w, bv.w);
        #pragma unroll
        for (int p = 0; p < 4; ++p){ acc[0][p]=b0; acc[1][p]=b1; acc[2][p]=b2; acc[3][p]=b3; }
    }
    #pragma unroll 4
    for (int i = 0; i < 64; ++i){
        ulonglong2 h01 = *(const ulonglong2*)&sh[i*132 + x0];
        ulonglong2 h23 = *(const ulonglong2*)&sh[i*132 + x0 + 4];
        float2 wab = *(const float2*)&sw[i*66 + o0];
        float2 wcd = *(const float2*)&sw[i*66 + o0 + 2];
        u64 w0 = fpack2(wab.x, wab.x), w1 = fpack2(wab.y, wab.y);
        u64 w2 = fpack2(wcd.x, wcd.x), w3 = fpack2(wcd.y, wcd.y);
        CMAD(0, w0) CMAD(1, w1) CMAD(2, w2) CMAD(3, w3)
    }
    #pragma unroll 4
    for (int ky = 0; ky < 16; ++ky){
        ulonglong2 A01 = *(const ulonglong2*)&sA[ky*132 + x0];
        ulonglong2 A23 = *(const ulonglong2*)&sA[ky*132 + x0 + 4];
        ulonglong2 B01 = *(const ulonglong2*)&sB[ky*132 + x0];
        ulonglong2 B23 = *(const ulonglong2*)&sB[ky*132 + x0 + 4];
        float2 ga = sg[ky*66 + o0],     gb2 = sg[ky*66 + o0 + 1];
        float2 gc = sg[ky*66 + o0 + 2], gd  = sg[ky*66 + o0 + 3];
        u64 gx0 = fpack2(ga.x, ga.x),  gy0 = fpack2(ga.y, ga.y);
        u64 gx1 = fpack2(gb2.x, gb2.x), gy1 = fpack2(gb2.y, gb2.y);
        u64 gx2 = fpack2(gc.x, gc.x),  gy2 = fpack2(gc.y, gc.y);
        u64 gx3 = fpack2(gd.x, gd.x),  gy3 = fpack2(gd.y, gd.y);
        IMAD2(0, gx0, gy0) IMAD2(1, gx1, gy1) IMAD2(2, gx2, gy2) IMAD2(3, gx3, gy3)
    }
    float* ob = hout + ((size_t)(b*64 + o0)*256 + y)*256 + xg2 + x0;
    #pragma unroll
    for (int oo = 0; oo < 4; ++oo){
        float2 p0 = funpack2(acc[oo][0]), p1 = funpack2(acc[oo][1]);
        float2 p2 = funpack2(acc[oo][2]), p3 = funpack2(acc[oo][3]);
        float4 v0 = make_float4(fmaxf(p0.x,0.f), fmaxf(p0.y,0.f), fmaxf(p1.x,0.f), fmaxf(p1.y,0.f));
        float4 v1 = make_float4(fmaxf(p2.x,0.f), fmaxf(p2.y,0.f), fmaxf(p3.x,0.f), fmaxf(p3.y,0.f));
        *(float4*)&ob[(size_t)oo*65536]     = v0;
        *(float4*)&ob[(size_t)oo*65536 + 4] = v1;
    }
}

// ---------------- fused MLP head ----------------
// block tile 128m x 64x; thread 4m x 8x; smem 87552 B
#define HMAD(mm, wd) \
    acc[mm][0]=ffma2(wd,h01.x,acc[mm][0]); acc[mm][1]=ffma2(wd,h01.y,acc[mm][1]); \
    acc[mm][2]=ffma2(wd,h23.x,acc[mm][2]); acc[mm][3]=ffma2(wd,h23.y,acc[mm][3]);

__global__ __launch_bounds__(256) void khead(
        const float* __restrict__ hin,
        const float* __restrict__ w1, const float* __restrict__ b1,
        const float* __restrict__ w2, const float* __restrict__ b2,
        float* __restrict__ out){
    extern __shared__ __align__(16) float dsm3[];
    float* sh   = dsm3;                            // [64 c][68]
    float* sw1t = sh + 64*68;                      // [64 c][130]  w1^T [c][m]
    float* shid = sw1t + 64*130;                   // [128 m][68]
    float* sw2s = shid + 128*68;                   // [384]
    float* sb1s = sw2s + 384;                      // [128]
    int tid = threadIdx.x;                         // 256
    int xc = (blockIdx.x & 3) << 6;
    int y  = (blockIdx.x >> 2) & 255;
    int b  = blockIdx.x >> 10;

    const float* hb = hin + ((size_t)(b*64)*256 + y)*256 + xc;
    for (int k = 0; k < 4; ++k){
        int idx = tid + k*256;                     // 1024 float4
        int c = idx >> 4, xq = (idx & 15)*4;
        *(float4*)&sh[c*68 + xq] = *(const float4*)&hb[(size_t)c*65536 + xq];
    }
    for (int k = 0; k < 32; ++k){
        int idx = tid + k*256;                     // 8192: sw1t[c][m] = w1[m][c]
        int c = idx & 63, m = idx >> 6;
        sw1t[c*130 + m] = w1[idx];
    }
    for (int idx = tid; idx < 384; idx += 256) sw2s[idx] = w2[idx];
    if (tid < 128) sb1s[tid] = b1[tid];
    __syncthreads();

    int w = tid >> 5, l = tid & 31;
    int m0 = ((w & 3)*8 + (l >> 2)) * 4;           // 32 m-groups
    int x0 = ((w >> 2)*4 + (l & 3)) * 8;           // 8 x-groups
    u64 acc[4][4];
    {
        float4 bv = *(const float4*)&sb1s[m0];
        u64 b0v = fpack2(bv.x,bv.x), b1v = fpack2(bv.y,bv.y);
        u64 b2v = fpack2(bv.z,bv.z), b3v = fpack2(bv.w,bv.w);
        #pragma unroll
        for (int p = 0; p < 4; ++p){ acc[0][p]=b0v; acc[1][p]=b1v; acc[2][p]=b2v; acc[3][p]=b3v; }
    }
    #pragma unroll 4
    for (int c = 0; c < 64; ++c){
        ulonglong2 h01 = *(const ulonglong2*)&sh[c*68 + x0];
        ulonglong2 h23 = *(const ulonglong2*)&sh[c*68 + x0 + 4];
        float2 wab = *(const float2*)&sw1t[c*130 + m0];
        float2 wcd = *(const float2*)&sw1t[c*130 + m0 + 2];
        u64 w0 = fpack2(wab.x,wab.x), w1d = fpack2(wab.y,wab.y);
        u64 w2d = fpack2(wcd.x,wcd.x), w3d = fpack2(wcd.y,wcd.y);
        HMAD(0, w0) HMAD(1, w1d) HMAD(2, w2d) HMAD(3, w3d)
    }
    #pragma unroll
    for (int mm = 0; mm < 4; ++mm){
        float2 p0 = funpack2(acc[mm][0]), p1 = funpack2(acc[mm][1]);
        float2 p2 = funpack2(acc[mm][2]), p3 = funpack2(acc[mm][3]);
        float4 v0 = make_float4(fmaxf(p0.x,0.f), fmaxf(p0.y,0.f), fmaxf(p1.x,0.f), fmaxf(p1.y,0.f));
        float4 v1 = make_float4(fmaxf(p2.x,0.f), fmaxf(p2.y,0.f), fmaxf(p3.x,0.f), fmaxf(p3.y,0.f));
        *(float4*)&shid[(m0+mm)*68 + x0]     = v0;
        *(float4*)&shid[(m0+mm)*68 + x0 + 4] = v1;
    }
    __syncthreads();
    if (tid < 192){
        int o = tid >> 6, xl = tid & 63;
        float a = b2[o];
        #pragma unroll 8
        for (int m = 0; m < 128; ++m)
            a = fmaf(shid[m*68 + xl], sw2s[o*128 + m], a);
        out[((size_t)(b*3 + o)*256 + y)*256 + xc + xl] = a;
    }
}

// ---------------- host ----------------
extern "C" void kernel_launch(void* const* d_in, const int* in_sizes, int n_in,
                              void* d_out, int out_size) {
    const float* x       = (const float*)d_in[0];
    const float* fc0_w   = (const float*)d_in[1];
    const float* fc0_b   = (const float*)d_in[2];
    const float* spec_re = (const float*)d_in[3];
    const float* spec_im = (const float*)d_in[4];
    const float* w_w     = (const float*)d_in[5];
    const float* w_b     = (const float*)d_in[6];
    const float* fc1_w   = (const float*)d_in[7];
    const float* fc1_b   = (const float*)d_in[8];
    const float* fc2_w   = (const float*)d_in[9];
    const float* fc2_b   = (const float*)d_in[10];

    float  *h0, *h1;
    float2 *f1, *mo, *mx, *G, *wt;
    cudaGetSymbolAddress((void**)&h0, g_h0);
    cudaGetSymbolAddress((void**)&h1, g_h1);
    cudaGetSymbolAddress((void**)&f1, g_f1);
    cudaGetSymbolAddress((void**)&mo, g_modes);
    cudaGetSymbolAddress((void**)&mx, g_mixed);
    cudaGetSymbolAddress((void**)&G,  g_G);
    cudaGetSymbolAddress((void**)&wt, g_wt);

    const int SM1 = 32*260*4 + 4096*8;             // 66048
    const int SM2 = (64*132 + 32*132 + 64*66)*4 + 16*66*8 + 64*4;   // 76288
    const int SM3 = (64*68 + 64*130 + 128*68)*4 + 384*4 + 128*4;    // 87552
    cudaFuncSetAttribute(kfwd1,  cudaFuncAttributeMaxDynamicSharedMemorySize, SM1);
    cudaFuncSetAttribute(kfused, cudaFuncAttributeMaxDynamicSharedMemorySize, SM2);
    cudaFuncSetAttribute(khead,  cudaFuncAttributeMaxDynamicSharedMemorySize, SM3);

    kprep<<<16, 256>>>();
    ktw<<<16384, 256>>>(spec_re, spec_im);
    kfc0<<<32768, 256>>>(x, fc0_w, fc0_b, h0);

    float* hin = h0;
    float* hout = h1;
    for (int d = 0; d < NDEPTH; ++d) {
        kfwd1<<<512, 256, SM1>>>(hin, f1);
        kfwd2<<<512, 512>>>(f1, mo);
        kmix<<<256, 256>>>(mo, wt + (size_t)d * 256 * 4096, mx);
        kinv1<<<2048, 256>>>(mx, G);
        kfused<<<4096, 256, SM2>>>(hin, G, w_w + d * 4096, w_b + d * 64, hout);
        float* t = hin; hin = hout; hout = t;
    }
    khead<<<8192, 256, SM3>>>(hin, fc1_w, fc1_b, fc2_w, fc2_b, (float*)d_out);
}